// round 1
// baseline (speedup 1.0000x reference)
#include <cuda_runtime.h>
#include <cstdint>

#define NEGF (-1e30f)
#define EPSF (1e-7f)

constexpr int Bc = 64;
constexpr int Tc = 1024;
constexpr int Cc = 128;
constexpr int Lc = 256;
constexpr int Sc = 2 * Lc + 1;   // 513
constexpr int BLANKc = Cc - 1;   // 127
constexpr int NT  = 128;         // threads per CTA (one CTA per batch)
constexpr int SPT = 4;           // states per thread; thread NT-1 also owns state 512

// logsumexp3 with the max's exp(0)==1 taken for free: 6 FMNMX + 2 EX2 + 1 LG2
__device__ __forceinline__ float lse3(float aa, float bb, float cc) {
    float hi  = fmaxf(aa, bb);
    float lo  = fminf(aa, bb);
    float m   = fmaxf(hi, cc);
    float t1  = fminf(hi, cc);
    float mid = fmaxf(t1, lo);
    float low = fminf(t1, lo);
    float sum = 1.0f + __expf(mid - m) + __expf(low - m);
    return m + __logf(sum);
}

__global__ __launch_bounds__(NT, 1) void ctc_loss_kernel(
    const int*   __restrict__ y_true,        // (B, L)
    const float* __restrict__ y_pred,        // (B, T, C)
    const int*   __restrict__ input_length,  // (B, 1)
    const int*   __restrict__ label_length,  // (B, 1)
    float*       __restrict__ out)           // (B, 1)
{
    const int b   = blockIdx.x;
    const int tid = threadIdx.x;
    const float* yp = y_pred + (size_t)b * Tc * Cc;
    const int*   yt = y_true + b * Lc;
    const int inLen  = input_length[b];
    const int labLen = label_length[b];
    const int Sval   = 2 * labLen + 1;

    __shared__ float  lp_sh[2][Cc];     // double-buffered log-prob row
    __shared__ float2 halo[2][NT + 1];  // halo[buf][tid+1] = (alpha[4t+2], alpha[4t+3])
    __shared__ float  res[2];

    if (tid == 0) {
        halo[0][0] = make_float2(NEGF, NEGF);
        halo[1][0] = make_float2(NEGF, NEGF);
        res[1] = NEGF;
    }

    const int ns    = (tid == NT - 1) ? (SPT + 1) : SPT;
    const int sbase = tid * SPT;

    // Per-state static data: extended label + skip-transition flag
    int  ext[SPT + 1];
    bool skp[SPT + 1];
    float a[SPT + 1];
    #pragma unroll
    for (int k = 0; k < SPT + 1; ++k) { ext[k] = BLANKc; skp[k] = false; a[k] = NEGF; }
    #pragma unroll
    for (int k = 0; k < SPT + 1; ++k) {
        int s = sbase + k;
        if ((s & 1) && s < Sc) {          // odd states carry labels
            int j = s >> 1;
            int lab = yt[j];
            ext[k] = lab;
            if (s >= 3) skp[k] = (lab != yt[j - 1]);  // non-blank & differs from s-2
        }
    }

    // ---- prologue: rows 0 and 1 into lp buffers, prefetch row 2 ----
    float p0 = yp[tid];
    lp_sh[0][tid] = __logf(p0 + EPSF);
    float p1 = yp[Cc + tid];
    lp_sh[1][tid] = __logf(p1 + EPSF);
    float pnext = yp[2 * Cc + tid];   // row 2 prefetch (T >= 3 guaranteed)
    __syncthreads();

    // alpha at t=0
    if (tid == 0) {
        a[0] = lp_sh[0][BLANKc];
        a[1] = (labLen > 0) ? lp_sh[0][ext[1]] : NEGF;
    }
    halo[0][tid + 1] = make_float2(a[2], a[3]);
    __syncthreads();

    // ---- main scan over time ----
    for (int t = 1; t < Tc; ++t) {
        const int rb = (t - 1) & 1;   // old-alpha halo buffer / freed lp buffer
        const int wb = t & 1;         // lp buffer holding row t / new-alpha halo buffer

        // stage log-probs for row t+1 into the freed buffer; prefetch row t+2
        if (t + 1 < Tc) lp_sh[rb][tid] = __logf(pnext + EPSF);
        if (t + 2 < Tc) pnext = yp[(size_t)(t + 2) * Cc + tid];

        if (sbase < Sval && t < inLen) {
            float2 h = halo[rb][tid];
            float prev2 = h.x;   // old alpha[sbase-2]
            float prev1 = h.y;   // old alpha[sbase-1]
            #pragma unroll
            for (int k = 0; k < SPT; ++k) {
                float aa = a[k];
                float cc = skp[k] ? prev2 : NEGF;
                float nv = lse3(aa, prev1, cc) + lp_sh[wb][ext[k]];
                a[k] = (sbase + k < Sval) ? nv : NEGF;
                prev2 = prev1; prev1 = aa;
            }
            if (tid == NT - 1) {  // state 512
                float aa = a[4];
                float nv = lse3(aa, prev1, NEGF) + lp_sh[wb][ext[4]];
                a[4] = (sbase + 4 < Sval) ? nv : NEGF;
            }
            halo[wb][tid + 1] = make_float2(a[2], a[3]);
        }
        __syncthreads();
    }

    // ---- epilogue: gather the two end states, combine ----
    const int se = 2 * labLen;
    if (se >= sbase && se < sbase + ns) res[0] = a[se - sbase];
    const int sl = se - 1;
    if (labLen > 0 && sl >= sbase && sl < sbase + ns) res[1] = a[sl - sbase];
    __syncthreads();

    if (tid == 0) {
        float eb = res[0], el = res[1];
        float m  = fmaxf(eb, el);
        float loss = -(m + __logf(__expf(eb - m) + __expf(el - m)));
        out[b] = loss;
    }
}

extern "C" void kernel_launch(void* const* d_in, const int* in_sizes, int n_in,
                              void* d_out, int out_size) {
    const int*   y_true       = (const int*)d_in[0];
    const float* y_pred       = (const float*)d_in[1];
    const int*   input_length = (const int*)d_in[2];
    const int*   label_length = (const int*)d_in[3];
    float* out = (float*)d_out;

    ctc_loss_kernel<<<Bc, NT>>>(y_true, y_pred, input_length, label_length, out);
}

// round 2
// speedup vs baseline: 1.2750x; 1.2750x over previous
#include <cuda_runtime.h>
#include <cstdint>

#define NEGF (-1e30f)
#define EPSF (1e-7f)
#define LN2F (0.69314718055994531f)

constexpr int Bc = 64;
constexpr int Tc = 1024;
constexpr int Cc = 128;
constexpr int Lc = 256;
constexpr int Sc = 2 * Lc + 1;   // 513
constexpr int BLANKc = Cc - 1;   // 127
constexpr int NT  = 128;
constexpr int SPT = 4;           // states per thread; thread NT-1 also owns state 512
constexpr int NBLK = 511;        // 2-step blocks covering t=1..1022; t=1023 done in epilogue

// log2-domain logsumexp: m + log2(1 + 2^(mid-m) + 2^(low-m)); 2 EX2 + 1 LG2
__device__ __forceinline__ float lse3_2(float aa, float bb, float cc) {
    float hi  = fmaxf(aa, bb);
    float lo  = fminf(aa, bb);
    float m   = fmaxf(hi, cc);
    float t1  = fminf(hi, cc);
    float mid = fmaxf(t1, lo);
    float low = fminf(t1, lo);
    return m + __log2f(1.0f + exp2f(mid - m) + exp2f(low - m));
}
// 2-input version for blank states (skip transition never allowed): 1 EX2 + 1 LG2
__device__ __forceinline__ float lse2_2(float aa, float bb) {
    float m = fmaxf(aa, bb);
    float l = fminf(aa, bb);
    return m + __log2f(1.0f + exp2f(l - m));
}

__global__ __launch_bounds__(NT, 1) void ctc_loss_kernel(
    const int*   __restrict__ y_true,        // (B, L)
    const float* __restrict__ y_pred,        // (B, T, C)
    const int*   __restrict__ input_length,  // (B, 1)
    const int*   __restrict__ label_length,  // (B, 1)
    float*       __restrict__ out)           // (B, 1)
{
    const int b   = blockIdx.x;
    const int tid = threadIdx.x;
    const float* __restrict__ yp = y_pred + (size_t)b * Tc * Cc;
    const int*   __restrict__ yt = y_true + b * Lc;
    const int inLen  = input_length[b];
    const int labLen = label_length[b];
    const int Sval   = 2 * labLen + 1;

    __shared__ float  lp[4][Cc];        // 4-deep ring of log2-prob rows, row r -> buffer r&3
    __shared__ float4 halo[2][NT + 1];  // halo[buf][tid+1] = old alpha[sbase..sbase+3] of thread tid
    __shared__ float  res[2];

    const int sbase = tid * SPT;

    // ---- static per-state tables for s = sbase-2+k, k in [0,6) ----
    // even k -> even state -> blank (lse2, ext=BLANK); odd k -> label state
    int  ext6[6];
    bool skp6[6];
    #pragma unroll
    for (int k = 0; k < 6; ++k) { ext6[k] = BLANKc; skp6[k] = false; }
    #pragma unroll
    for (int k = 1; k < 6; k += 2) {
        int s = sbase - 2 + k;
        if (s >= 1 && s < Sc) {
            int j   = s >> 1;
            int lab = yt[j];
            ext6[k] = lab;
            if (s >= 3) skp6[k] = (lab != yt[j - 1]);
        }
    }

    // ---- alpha at t=0 (log2 domain) ----
    float a0 = NEGF, a1 = NEGF, a2 = NEGF, a3 = NEGF, a4 = NEGF;
    if (tid == 0) {
        a0 = __log2f(yp[BLANKc] + EPSF);
        if (labLen > 0) a1 = __log2f(yp[yt[0]] + EPSF);
    }

    // ---- prologue: stage lp rows 1,2; prefetch rows 3..6 ----
    lp[1][tid] = __log2f(yp[Cc + tid] + EPSF);
    lp[2][tid] = __log2f(yp[2 * Cc + tid] + EPSF);
    float pA0 = yp[3 * Cc + tid], pA1 = yp[4 * Cc + tid];
    float pB0 = yp[5 * Cc + tid], pB1 = yp[6 * Cc + tid];

    halo[0][tid + 1] = make_float4(a0, a1, a2, a3);
    if (tid == 0) {
        halo[0][0] = make_float4(NEGF, NEGF, NEGF, NEGF);
        halo[1][0] = make_float4(NEGF, NEGF, NEGF, NEGF);
        res[0] = NEGF; res[1] = NEGF;
    }
    __syncthreads();

    const bool own = (sbase < Sval);
    const bool last = (tid == NT - 1);

    // ---- main scan: 2 time steps per barrier ----
    for (int j = 0; j < NBLK; ++j) {
        const int t1 = 2 * j + 1, t2 = 2 * j + 2;
        const float* __restrict__ lp1 = lp[t1 & 3];
        const float* __restrict__ lp2 = lp[t2 & 3];

        // stage lp rows t+2,t+3 for next block (pA arrived ~1.5 blocks ago)
        lp[(t1 + 2) & 3][tid] = __log2f(pA0 + EPSF);
        lp[(t2 + 2) & 3][tid] = __log2f(pA1 + EPSF);
        pA0 = pB0; pA1 = pB1;
        {
            int r1 = min(2 * j + 7, Tc - 1);
            int r2 = min(2 * j + 8, Tc - 1);
            pB0 = yp[(size_t)r1 * Cc + tid];
            pB1 = yp[(size_t)r2 * Cc + tid];
        }

        if (own) {
            float4 h = halo[j & 1][tid];
            // o[k] = old alpha[sbase-4+k]
            float o[9];
            o[0] = h.x; o[1] = h.y; o[2] = h.z; o[3] = h.w;
            o[4] = a0; o[5] = a1; o[6] = a2; o[7] = a3; o[8] = a4;

            const bool act1 = (t1 < inLen);
            const bool act2 = (t2 < inLen);

            // step t1: states s = sbase-2+k, k=0..5 (2 redundant)
            float n[6];
            #pragma unroll
            for (int k = 0; k < 6; ++k) {
                int s = sbase - 2 + k;
                float v;
                if ((k & 1) == 0) v = lse2_2(o[k + 2], o[k + 1]);                       // blank
                else              v = lse3_2(o[k + 2], o[k + 1], skp6[k] ? o[k] : NEGF); // label
                v += lp1[ext6[k]];
                v = ((unsigned)s < (unsigned)Sval) ? v : NEGF;
                n[k] = act1 ? v : o[k + 2];
            }
            float n512 = NEGF;
            if (last) {
                float v = lse2_2(o[8], o[7]) + lp1[BLANKc];
                v = (512 < Sval) ? v : NEGF;
                n512 = act1 ? v : o[8];
            }

            // step t2: states s = sbase+k, k=0..3 (+512 for last thread)
            #pragma unroll
            for (int k = 0; k < 4; ++k) {
                int s = sbase + k;
                float v;
                if ((k & 1) == 0) v = lse2_2(n[k + 2], n[k + 1]);
                else              v = lse3_2(n[k + 2], n[k + 1], skp6[k + 2] ? n[k] : NEGF);
                v += lp2[ext6[k + 2]];
                v = (s < Sval) ? v : NEGF;
                float r = act2 ? v : n[k + 2];
                if (k == 0) a0 = r; else if (k == 1) a1 = r;
                else if (k == 2) a2 = r; else a3 = r;
            }
            if (last) {
                float v = lse2_2(n512, n[5]) + lp2[BLANKc];
                v = (512 < Sval) ? v : NEGF;
                a4 = act2 ? v : n512;
            }
        }

        halo[(j + 1) & 1][tid + 1] = make_float4(a0, a1, a2, a3);
        __syncthreads();
    }

    // ---- final step t=1023 (single) ----
    {
        const int t = Tc - 1;
        const float* __restrict__ lpf = lp[t & 3];
        const bool act = (t < inLen);
        if (own) {
            float4 h = halo[NBLK & 1][tid];
            float o[9];
            o[0] = h.x; o[1] = h.y; o[2] = h.z; o[3] = h.w;
            o[4] = a0; o[5] = a1; o[6] = a2; o[7] = a3; o[8] = a4;
            float r[5];
            #pragma unroll
            for (int k = 0; k < 4; ++k) {
                int s = sbase + k;
                float v;
                if ((k & 1) == 0) v = lse2_2(o[k + 4], o[k + 3]);
                else              v = lse3_2(o[k + 4], o[k + 3], skp6[k + 2] ? o[k + 2] : NEGF);
                v += lpf[ext6[k + 2]];
                v = (s < Sval) ? v : NEGF;
                r[k] = act ? v : o[k + 4];
            }
            r[4] = a4;
            if (last) {
                float v = lse2_2(o[8], o[7]) + lpf[BLANKc];
                v = (512 < Sval) ? v : NEGF;
                r[4] = act ? v : o[8];
            }
            a0 = r[0]; a1 = r[1]; a2 = r[2]; a3 = r[3]; a4 = r[4];
        }
    }

    // ---- epilogue: gather end states, combine ----
    const int ns = last ? (SPT + 1) : SPT;
    const int se = 2 * labLen;
    if (se >= sbase && se < sbase + ns) {
        int k = se - sbase;
        res[0] = (k == 0) ? a0 : (k == 1) ? a1 : (k == 2) ? a2 : (k == 3) ? a3 : a4;
    }
    const int sl = se - 1;
    if (labLen > 0 && sl >= sbase && sl < sbase + ns) {
        int k = sl - sbase;
        res[1] = (k == 0) ? a0 : (k == 1) ? a1 : (k == 2) ? a2 : (k == 3) ? a3 : a4;
    }
    __syncthreads();

    if (tid == 0) {
        out[b] = -LN2F * lse2_2(res[0], res[1]);
    }
}

extern "C" void kernel_launch(void* const* d_in, const int* in_sizes, int n_in,
                              void* d_out, int out_size) {
    const int*   y_true       = (const int*)d_in[0];
    const float* y_pred       = (const float*)d_in[1];
    const int*   input_length = (const int*)d_in[2];
    const int*   label_length = (const int*)d_in[3];
    float* out = (float*)d_out;

    ctc_loss_kernel<<<Bc, NT>>>(y_true, y_pred, input_length, label_length, out);
}